// round 1
// baseline (speedup 1.0000x reference)
#include <cuda_runtime.h>

// LocalConvolutionMix: involution-style per-pixel local conv, two branches
// (3x3 pad 1, 5x5 pad 2) sharing one x tile.
// x:  [N=4, C=256, H=56, W=56] f32
// w1: [N, heads=1, wc=32, 9,  H, W]
// w2: [N, heads=1, wc=32, 25, H, W]
// out:[N, 2, heads=1, C, H, W]
//
// Block = (56, 8) threads, one block per (h_tile, v, n).
// Each thread produces 16 outputs: 8 channel groups x 2 branches at one (h,w).

#define N_   4
#define C_   256
#define H_   56
#define W_   56
#define WC_  32
#define G_   8          // C_/WC_
#define TH_  8          // rows per block
#define HW_  (H_*W_)

__global__ __launch_bounds__(W_*TH_, 2)
void localconv_mix_kernel(const float* __restrict__ x,
                          const float* __restrict__ w1,
                          const float* __restrict__ w2,
                          float* __restrict__ out)
{
    // smem x tile: 8 channel-groups, 12 rows (TH+4 halo), 60 cols (W+4 halo)
    __shared__ float xs[G_][TH_ + 4][W_ + 4];

    const int tx = threadIdx.x;          // 0..55  -> w
    const int ty = threadIdx.y;          // 0..7   -> row within tile
    const int h0 = blockIdx.x * TH_;     // tile base row
    const int v  = blockIdx.y;           // 0..31
    const int n  = blockIdx.z;           // 0..3

    // ---- stage x tile: channels c = g*32+v, rows h0-2..h0+9, cols -2..57 ----
    const int tid = ty * W_ + tx;                 // 0..447
    const int nthreads = W_ * TH_;                // 448
    const int tile_elems = G_ * (TH_ + 4) * (W_ + 4);  // 5760
    float* xs_flat = &xs[0][0][0];

    #pragma unroll 1
    for (int e = tid; e < tile_elems; e += nthreads) {
        int g   = e / ((TH_ + 4) * (W_ + 4));
        int rem = e - g * ((TH_ + 4) * (W_ + 4));
        int r   = rem / (W_ + 4);
        int col = rem - r * (W_ + 4);
        int hh = h0 - 2 + r;
        int ww = col - 2;
        float val = 0.0f;
        if (hh >= 0 && hh < H_ && ww >= 0 && ww < W_) {
            int c = g * WC_ + v;
            val = x[(((size_t)n * C_ + c) * H_ + hh) * W_ + ww];
        }
        xs_flat[e] = val;
    }
    __syncthreads();

    const int h = h0 + ty;
    const int w = tx;

    // weight base pointers for this (n, v, h, w)
    const size_t pix = (size_t)h * W_ + w;
    const float* w2p = w2 + ((size_t)(n * WC_ + v) * 25) * HW_ + pix;
    const float* w1p = w1 + ((size_t)(n * WC_ + v) * 9)  * HW_ + pix;

    float a1[G_], a2[G_];
    #pragma unroll
    for (int g = 0; g < G_; g++) { a1[g] = 0.0f; a2[g] = 0.0f; }

    // 25 taps; the center 3x3 (ki,kj in [1,3]) also feeds branch 1
    #pragma unroll
    for (int ki = 0; ki < 5; ki++) {
        #pragma unroll
        for (int kj = 0; kj < 5; kj++) {
            const int k2 = ki * 5 + kj;
            const float wv2 = __ldg(w2p + (size_t)k2 * HW_);

            float xv[G_];
            #pragma unroll
            for (int g = 0; g < G_; g++)
                xv[g] = xs[g][ty + ki][tx + kj];

            #pragma unroll
            for (int g = 0; g < G_; g++)
                a2[g] = fmaf(wv2, xv[g], a2[g]);

            if (ki >= 1 && ki <= 3 && kj >= 1 && kj <= 3) {
                const int k1 = (ki - 1) * 3 + (kj - 1);
                const float wv1 = __ldg(w1p + (size_t)k1 * HW_);
                #pragma unroll
                for (int g = 0; g < G_; g++)
                    a1[g] = fmaf(wv1, xv[g], a1[g]);
            }
        }
    }

    // out[n][br][0][c][h][w], c = g*32+v
    #pragma unroll
    for (int g = 0; g < G_; g++) {
        const int c = g * WC_ + v;
        out[(((size_t)n * 2 + 0) * C_ + c) * HW_ + pix] = a1[g];
        out[(((size_t)n * 2 + 1) * C_ + c) * HW_ + pix] = a2[g];
    }
}

extern "C" void kernel_launch(void* const* d_in, const int* in_sizes, int n_in,
                              void* d_out, int out_size)
{
    const float* x  = (const float*)d_in[0];
    const float* w1 = (const float*)d_in[1];
    const float* w2 = (const float*)d_in[2];
    float* out = (float*)d_out;

    dim3 block(W_, TH_);          // 448 threads
    dim3 grid(H_ / TH_, WC_, N_); // (7, 32, 4) = 896 blocks
    localconv_mix_kernel<<<grid, block>>>(x, w1, w2, out);
}